// round 6
// baseline (speedup 1.0000x reference)
#include <cuda_runtime.h>
#include <cuda_bf16.h>

#define NTOK   4096
#define DMODEL 512
#define NH     8
#define DHD    64
#define WSZ    128
#define NP     32
#define DISP   64
#define QKV_LD 1536
#define MTOT   32768

// ---------------------------------------------------------------------------
// Scratch (device globals — allocation-free per harness rules)
// ---------------------------------------------------------------------------
__device__ float g_qkv[(size_t)MTOT * QKV_LD];            // gemm0 out (f32)
__device__ __nv_bfloat16 g_xhi[(size_t)MTOT * DMODEL];    // shifted x, hi plane
__device__ __nv_bfloat16 g_xlo[(size_t)MTOT * DMODEL];    // shifted x, lo plane
__device__ __nv_bfloat16 g_ahi[(size_t)MTOT * DMODEL];    // attn out, hi plane
__device__ __nv_bfloat16 g_alo[(size_t)MTOT * DMODEL];    // attn out, lo plane
__device__ __nv_bfloat16 g_wqkv_hi[(size_t)QKV_LD * DMODEL];  // W^T [n][k]
__device__ __nv_bfloat16 g_wqkv_lo[(size_t)QKV_LD * DMODEL];
__device__ __nv_bfloat16 g_wout_hi[(size_t)DMODEL * DMODEL];
__device__ __nv_bfloat16 g_wout_lo[(size_t)DMODEL * DMODEL];

// ---------------------------------------------------------------------------
// helpers
// ---------------------------------------------------------------------------
__device__ __forceinline__ unsigned smem_u32(const void* p) {
    return (unsigned)__cvta_generic_to_shared(p);
}
__device__ __forceinline__ unsigned pack2(__nv_bfloat16 a, __nv_bfloat16 b) {
    unsigned short ua = *(unsigned short*)&a, ub = *(unsigned short*)&b;
    return (unsigned)ua | ((unsigned)ub << 16);
}
__device__ __forceinline__ unsigned packf2(float a, float b) {
    __nv_bfloat162 v = __float22bfloat162_rn(make_float2(a, b));
    return *(unsigned*)&v;
}
__device__ __forceinline__ void mma_bf16(float* d, const unsigned* a, const unsigned* b) {
    asm volatile(
        "mma.sync.aligned.m16n8k16.row.col.f32.bf16.bf16.f32 "
        "{%0,%1,%2,%3}, {%4,%5,%6,%7}, {%8,%9}, {%0,%1,%2,%3};\n"
        : "+f"(d[0]), "+f"(d[1]), "+f"(d[2]), "+f"(d[3])
        : "r"(a[0]), "r"(a[1]), "r"(a[2]), "r"(a[3]), "r"(b[0]), "r"(b[1]));
}
__device__ __forceinline__ void ldsm4(unsigned* r, unsigned a) {
    asm volatile("ldmatrix.sync.aligned.m8n8.x4.shared.b16 {%0,%1,%2,%3}, [%4];"
        : "=r"(r[0]), "=r"(r[1]), "=r"(r[2]), "=r"(r[3]) : "r"(a));
}
__device__ __forceinline__ void ldsm4t(unsigned* r, unsigned a) {
    asm volatile("ldmatrix.sync.aligned.m8n8.x4.trans.shared.b16 {%0,%1,%2,%3}, [%4];"
        : "=r"(r[0]), "=r"(r[1]), "=r"(r[2]), "=r"(r[3]) : "r"(a));
}
#define CP16(dst, src) \
    asm volatile("cp.async.ca.shared.global [%0], [%1], 16;\n" :: "r"(dst), "l"(src))

// ---------------------------------------------------------------------------
// Prep 1: shifted x -> bf16 hi/lo planes.
// ---------------------------------------------------------------------------
__global__ void __launch_bounds__(128)
split_x_shift(const float* __restrict__ x)
{
    const int row = blockIdx.x;
    const int b = row >> 12, n = row & 4095;
    const float4* src = (const float4*)(x + (size_t)((b << 12) | ((n + DISP) & 4095)) * DMODEL);
    float4 v = src[threadIdx.x];
    __nv_bfloat16 h0 = __float2bfloat16(v.x), h1 = __float2bfloat16(v.y);
    __nv_bfloat16 h2 = __float2bfloat16(v.z), h3 = __float2bfloat16(v.w);
    __nv_bfloat16 l0 = __float2bfloat16(v.x - __bfloat162float(h0));
    __nv_bfloat16 l1 = __float2bfloat16(v.y - __bfloat162float(h1));
    __nv_bfloat16 l2 = __float2bfloat16(v.z - __bfloat162float(h2));
    __nv_bfloat16 l3 = __float2bfloat16(v.w - __bfloat162float(h3));
    const size_t o = (size_t)row * DMODEL + threadIdx.x * 4;
    *(uint2*)&g_xhi[o] = make_uint2(pack2(h0, h1), pack2(h2, h3));
    *(uint2*)&g_xlo[o] = make_uint2(pack2(l0, l1), pack2(l2, l3));
}

// ---------------------------------------------------------------------------
// Prep 2: W [K][N] -> W^T [N][K] bf16 hi/lo planes.
// ---------------------------------------------------------------------------
template<int WHICH>
__global__ void __launch_bounds__(1024)
split_wT(const float* __restrict__ W)
{
    constexpr int K = DMODEL;
    constexpr int N = (WHICH == 0) ? QKV_LD : DMODEL;
    __nv_bfloat16* hi = (WHICH == 0) ? g_wqkv_hi : g_wout_hi;
    __nv_bfloat16* lo = (WHICH == 0) ? g_wqkv_lo : g_wout_lo;

    __shared__ float t[32][33];
    const int n0 = blockIdx.x << 5, k0 = blockIdx.y << 5;
    const int tx = threadIdx.x, ty = threadIdx.y;
    t[ty][tx] = W[(size_t)(k0 + ty) * N + n0 + tx];
    __syncthreads();
    const float v = t[tx][ty];
    const size_t o = (size_t)(n0 + ty) * K + k0 + tx;
    __nv_bfloat16 h = __float2bfloat16(v);
    hi[o] = h;
    lo[o] = __float2bfloat16(v - __bfloat162float(h));
}

// ---------------------------------------------------------------------------
// 3-term bf16 GEMM. Block tile 128(M)x256(N)x16(K), 256 thr, warps 2(M)x4(N),
// warp tile 64x64. ldmatrix fragments, 3-stage cp.async pipeline, dyn smem.
// MODE 0: A = g_x{hi,lo}, B = Wqkv^T, C = g_qkv            (grid 6 x 256)
// MODE 1: A = g_a{hi,lo}, B = Wout^T, C = out (+roll,bias) (grid 2 x 256)
// ---------------------------------------------------------------------------
#define PITCH   24
#define PITCHB  48                    // bytes per row
#define AH_OFF  0
#define AL_OFF  (128 * PITCHB)        // 6144
#define BH_OFF  (2 * 128 * PITCHB)    // 12288
#define BL_OFF  (BH_OFF + 256 * PITCHB)  // 24576
#define STAGE_B (BL_OFF + 256 * PITCHB)  // 36864
#define GSMEM_B (3 * STAGE_B)            // 110592
#define NKIT    (DMODEL / 16)

template<int MODE>
__global__ void __launch_bounds__(256)
gemm_bf16(const float* __restrict__ bias, float* __restrict__ Cout)
{
    const __nv_bfloat16* __restrict__ Ahi = (MODE == 0) ? g_xhi : g_ahi;
    const __nv_bfloat16* __restrict__ Alo = (MODE == 0) ? g_xlo : g_alo;
    const __nv_bfloat16* __restrict__ Bhi = (MODE == 0) ? g_wqkv_hi : g_wout_hi;
    const __nv_bfloat16* __restrict__ Blo = (MODE == 0) ? g_wqkv_lo : g_wout_lo;
    float* __restrict__ C = (MODE == 0) ? (float*)g_qkv : Cout;
    constexpr int LDC = (MODE == 0) ? QKV_LD : DMODEL;

    extern __shared__ __align__(16) char smg[];
    const unsigned sbase = smem_u32(smg);

    const int tid  = threadIdx.x;
    const int lane = tid & 31;
    const int wid  = tid >> 5;
    const int g    = lane >> 2;
    const int c    = lane & 3;
    const int wm   = (wid >> 2) * 64;   // 0 / 64
    const int wn   = (wid & 3) * 64;    // 0..192

    const int m0 = blockIdx.y << 7;
    const int n0 = blockIdx.x << 8;

    // cp.async per-thread mapping
    const int lr = tid >> 1;            // 0..127
    const int lh = (tid & 1) * 8;       // 0 / 8
    const size_t agm  = (size_t)(m0 + lr) * DMODEL + lh;
    const size_t bgm  = (size_t)(n0 + lr) * DMODEL + lh;
    const size_t bgm2 = bgm + (size_t)128 * DMODEL;
    const unsigned ld_off = (unsigned)(lr * PITCHB + lh * 2);
    const unsigned dAh = sbase + AH_OFF + ld_off;
    const unsigned dAl = sbase + AL_OFF + ld_off;
    const unsigned dBh = sbase + BH_OFF + ld_off;
    const unsigned dBl = sbase + BL_OFF + ld_off;

    // ldmatrix lane offsets (bytes)
    const unsigned aoff = (unsigned)((wm + (lane & 15)) * PITCHB + (lane & 16));
    const unsigned boff = (unsigned)((wn + (lane & 7) + ((lane & 16) >> 1)) * PITCHB
                                     + ((lane & 8) << 1));
    const unsigned lAh = sbase + AH_OFF + aoff;
    const unsigned lAl = sbase + AL_OFF + aoff;
    const unsigned lBh = sbase + BH_OFF + boff;
    const unsigned lBl = sbase + BL_OFF + boff;

    float acc[4][8][4];
#pragma unroll
    for (int mt = 0; mt < 4; mt++)
#pragma unroll
        for (int nt = 0; nt < 8; nt++)
#pragma unroll
            for (int i = 0; i < 4; i++) acc[mt][nt][i] = 0.f;

    // stage loader: one ktile (K=16) of all 4 planes
#define LOAD_STAGE(kt)                                                         \
    do {                                                                       \
        if ((kt) < NKIT) {                                                     \
            const unsigned so = (unsigned)((kt) % 3) * STAGE_B;                \
            const size_t ka = agm + (kt) * 16;                                 \
            const size_t kb = bgm + (kt) * 16;                                 \
            const size_t kb2 = bgm2 + (kt) * 16;                               \
            CP16(dAh + so, Ahi + ka);                                          \
            CP16(dAl + so, Alo + ka);                                          \
            CP16(dBh + so, Bhi + kb);                                          \
            CP16(dBh + so + 128 * PITCHB, Bhi + kb2);                          \
            CP16(dBl + so, Blo + kb);                                          \
            CP16(dBl + so + 128 * PITCHB, Blo + kb2);                          \
        }                                                                      \
        asm volatile("cp.async.commit_group;\n");                              \
    } while (0)

    LOAD_STAGE(0);
    LOAD_STAGE(1);

#pragma unroll 1
    for (int kt = 0; kt < NKIT; kt++) {
        asm volatile("cp.async.wait_group 1;\n");
        __syncthreads();
        LOAD_STAGE(kt + 2);

        const unsigned so = (unsigned)(kt % 3) * STAGE_B;
        unsigned Ah[4][4], Al[4][4];
#pragma unroll
        for (int mt = 0; mt < 4; mt++) {
            ldsm4(Ah[mt], lAh + so + mt * 16 * PITCHB);
            ldsm4(Al[mt], lAl + so + mt * 16 * PITCHB);
        }
#pragma unroll
        for (int p = 0; p < 4; p++) {
            unsigned Bh[4], Bl[4];
            ldsm4(Bh, lBh + so + p * 16 * PITCHB);
            ldsm4(Bl, lBl + so + p * 16 * PITCHB);
#pragma unroll
            for (int mt = 0; mt < 4; mt++) {
#pragma unroll
                for (int e = 0; e < 2; e++) {
                    float* d = acc[mt][2 * p + e];
                    mma_bf16(d, Al[mt], Bh + 2 * e);
                    mma_bf16(d, Ah[mt], Bl + 2 * e);
                    mma_bf16(d, Ah[mt], Bh + 2 * e);
                }
            }
        }
        __syncthreads();
    }
#undef LOAD_STAGE

    float2 bv[8];
    if (MODE == 1) {
#pragma unroll
        for (int nt = 0; nt < 8; nt++)
            bv[nt] = *(const float2*)&bias[n0 + wn + nt * 8 + 2 * c];
    }
#pragma unroll
    for (int mt = 0; mt < 4; mt++) {
#pragma unroll
        for (int half = 0; half < 2; half++) {
            const int row = m0 + wm + mt * 16 + g + half * 8;
            long crow;
            if (MODE == 1) {
                const int bb = row >> 12, nn = row & 4095;
                crow = (long)((bb << 12) | ((nn + DISP) & 4095)) * LDC;
            } else {
                crow = (long)row * LDC;
            }
#pragma unroll
            for (int nt = 0; nt < 8; nt++) {
                float x = acc[mt][nt][half * 2 + 0];
                float y = acc[mt][nt][half * 2 + 1];
                if (MODE == 1) { x += bv[nt].x; y += bv[nt].y; }
                *(float2*)&C[crow + n0 + wn + nt * 8 + 2 * c] = make_float2(x, y);
            }
        }
    }
}

// ---------------------------------------------------------------------------
// Tensor-core windowed attention (unchanged from R5 — known good).
// ---------------------------------------------------------------------------
#define APIT 72
#define APITB (APIT * 2)
#define PLANE_B (128 * APITB)
#define ATTN_SMEM_B (6 * PLANE_B)

__global__ void __launch_bounds__(256)
attn_kernel(const float* __restrict__ pos_emb)
{
    extern __shared__ __align__(16) char smc[];
    __nv_bfloat16* Qh = (__nv_bfloat16*)(smc + 0 * PLANE_B);
    __nv_bfloat16* Ql = (__nv_bfloat16*)(smc + 1 * PLANE_B);
    __nv_bfloat16* Kh = (__nv_bfloat16*)(smc + 2 * PLANE_B);
    __nv_bfloat16* Kl = (__nv_bfloat16*)(smc + 3 * PLANE_B);
    __nv_bfloat16* Vh = (__nv_bfloat16*)(smc + 4 * PLANE_B);
    __nv_bfloat16* Vl = (__nv_bfloat16*)(smc + 5 * PLANE_B);
    __shared__ float pe[2 * WSZ - 1];

    const int tid  = threadIdx.x;
    const int lane = tid & 31;
    const int w    = tid >> 5;
    const int g    = lane >> 2;
    const int c    = lane & 3;
    const int blk  = blockIdx.x;
    const int pi   = blk & 31;
    const int h    = (blk >> 5) & 7;
    const int b    = blk >> 8;

    for (int i = tid; i < 2 * WSZ - 1; i += 256) pe[i] = pos_emb[i];

    {
        const int tok = tid >> 1;
        const int d0  = (tid & 1) * 32;
        const size_t rbase = ((size_t)(b << 12) + tok * NP + pi) * QKV_LD + h * DHD;
        const int so = tok * APIT;
#pragma unroll
        for (int j = 0; j < 8; j += 2) {
#pragma unroll
            for (int u = 0; u < 2; u++) {
                const int d = d0 + (j + u) * 4;
                float4 q = *(const float4*)&g_qkv[rbase + d];
                float4 k = *(const float4*)&g_qkv[rbase + 512 + d];
                float4 v = *(const float4*)&g_qkv[rbase + 1024 + d];
                q.x *= 0.125f; q.y *= 0.125f; q.z *= 0.125f; q.w *= 0.125f;
                unsigned qh01 = packf2(q.x, q.y), qh23 = packf2(q.z, q.w);
                float qr0 = __uint_as_float(qh01 << 16), qr1 = __uint_as_float(qh01 & 0xffff0000u);
                float qr2 = __uint_as_float(qh23 << 16), qr3 = __uint_as_float(qh23 & 0xffff0000u);
                *(uint2*)&Qh[so + d] = make_uint2(qh01, qh23);
                *(uint2*)&Ql[so + d] = make_uint2(packf2(q.x - qr0, q.y - qr1),
                                                  packf2(q.z - qr2, q.w - qr3));
                unsigned kh01 = packf2(k.x, k.y), kh23 = packf2(k.z, k.w);
                float kr0 = __uint_as_float(kh01 << 16), kr1 = __uint_as_float(kh01 & 0xffff0000u);
                float kr2 = __uint_as_float(kh23 << 16), kr3 = __uint_as_float(kh23 & 0xffff0000u);
                *(uint2*)&Kh[so + d] = make_uint2(kh01, kh23);
                *(uint2*)&Kl[so + d] = make_uint2(packf2(k.x - kr0, k.y - kr1),
                                                  packf2(k.z - kr2, k.w - kr3));
                unsigned vh01 = packf2(v.x, v.y), vh23 = packf2(v.z, v.w);
                float vr0 = __uint_as_float(vh01 << 16), vr1 = __uint_as_float(vh01 & 0xffff0000u);
                float vr2 = __uint_as_float(vh23 << 16), vr3 = __uint_as_float(vh23 & 0xffff0000u);
                *(uint2*)&Vh[so + d] = make_uint2(vh01, vh23);
                *(uint2*)&Vl[so + d] = make_uint2(packf2(v.x - vr0, v.y - vr1),
                                                  packf2(v.z - vr2, v.w - vr3));
            }
        }
    }
    __syncthreads();

    float accS[16][4];
#pragma unroll
    for (int nt = 0; nt < 16; nt++)
#pragma unroll
        for (int i = 0; i < 4; i++) accS[nt][i] = 0.f;

    const unsigned qoff = (unsigned)((w * 16 + (lane & 15)) * APITB + (lane & 16));
    const unsigned koff = (unsigned)(((lane & 7) + ((lane & 16) >> 1)) * APITB
                                     + ((lane & 8) << 1));
    const unsigned uQh = smem_u32(Qh) + qoff, uQl = smem_u32(Ql) + qoff;
    const unsigned uKh = smem_u32(Kh) + koff, uKl = smem_u32(Kl) + koff;

#pragma unroll
    for (int kc = 0; kc < 4; kc++) {
        unsigned qh[4], ql[4];
        ldsm4(qh, uQh + kc * 32);
        ldsm4(ql, uQl + kc * 32);
#pragma unroll
        for (int p = 0; p < 8; p++) {
            unsigned kh[4], kl[4];
            ldsm4(kh, uKh + p * 16 * APITB + kc * 32);
            ldsm4(kl, uKl + p * 16 * APITB + kc * 32);
            mma_bf16(accS[2 * p + 0], ql, kh + 0);
            mma_bf16(accS[2 * p + 0], qh, kl + 0);
            mma_bf16(accS[2 * p + 0], qh, kh + 0);
            mma_bf16(accS[2 * p + 1], ql, kh + 2);
            mma_bf16(accS[2 * p + 1], qh, kl + 2);
            mma_bf16(accS[2 * p + 1], qh, kh + 2);
        }
    }

    const int i0 = w * 16 + g;
    const int i1 = i0 + 8;
    const bool q0 = (i0 >= 64), q1 = (i1 >= 64);
    float mx0 = -3.0e38f, mx1 = -3.0e38f;
#pragma unroll
    for (int nt = 0; nt < 16; nt++) {
#pragma unroll
        for (int e = 0; e < 2; e++) {
            const int j = nt * 8 + 2 * c + e;
            const bool jq = (j >= 64);
            float s0 = accS[nt][e]     + pe[j - i0 + (WSZ - 1)];
            float s1 = accS[nt][2 + e] + pe[j - i1 + (WSZ - 1)];
            if (q0 != jq) s0 -= 1e9f;
            if (q1 != jq) s1 -= 1e9f;
            accS[nt][e] = s0;     mx0 = fmaxf(mx0, s0);
            accS[nt][2 + e] = s1; mx1 = fmaxf(mx1, s1);
        }
    }
    mx0 = fmaxf(mx0, __shfl_xor_sync(0xffffffffu, mx0, 1));
    mx0 = fmaxf(mx0, __shfl_xor_sync(0xffffffffu, mx0, 2));
    mx1 = fmaxf(mx1, __shfl_xor_sync(0xffffffffu, mx1, 1));
    mx1 = fmaxf(mx1, __shfl_xor_sync(0xffffffffu, mx1, 2));
    float sm0 = 0.f, sm1 = 0.f;
#pragma unroll
    for (int nt = 0; nt < 16; nt++) {
#pragma unroll
        for (int e = 0; e < 2; e++) {
            float e0 = __expf(accS[nt][e] - mx0);
            float e1 = __expf(accS[nt][2 + e] - mx1);
            accS[nt][e] = e0;     sm0 += e0;
            accS[nt][2 + e] = e1; sm1 += e1;
        }
    }
    sm0 += __shfl_xor_sync(0xffffffffu, sm0, 1);
    sm0 += __shfl_xor_sync(0xffffffffu, sm0, 2);
    sm1 += __shfl_xor_sync(0xffffffffu, sm1, 1);
    sm1 += __shfl_xor_sync(0xffffffffu, sm1, 2);
    const float inv0 = 1.0f / sm0, inv1 = 1.0f / sm1;
#pragma unroll
    for (int nt = 0; nt < 16; nt++) {
        accS[nt][0] *= inv0; accS[nt][1] *= inv0;
        accS[nt][2] *= inv1; accS[nt][3] *= inv1;
    }

    float out[8][4];
#pragma unroll
    for (int nt = 0; nt < 8; nt++)
#pragma unroll
        for (int i = 0; i < 4; i++) out[nt][i] = 0.f;

    const unsigned voff = (unsigned)((lane & 15) * APITB + (lane & 16));
    const unsigned uVh = smem_u32(Vh) + voff, uVl = smem_u32(Vl) + voff;

#pragma unroll
    for (int kc = 0; kc < 8; kc++) {
        unsigned a_hi[4], a_lo[4];
#pragma unroll
        for (int q = 0; q < 4; q++) {
            const int nt = 2 * kc + (q >> 1);
            const int e0 = (q & 1) * 2;
            const float v0 = accS[nt][e0], v1 = accS[nt][e0 + 1];
            const unsigned hh = packf2(v0, v1);
            a_hi[q] = hh;
            const float r0 = __uint_as_float(hh << 16);
            const float r1 = __uint_as_float(hh & 0xffff0000u);
            a_lo[q] = packf2(v0 - r0, v1 - r1);
        }
#pragma unroll
        for (int p = 0; p < 4; p++) {
            unsigned vh[4], vl[4];
            ldsm4t(vh, uVh + kc * 16 * APITB + p * 32);
            ldsm4t(vl, uVl + kc * 16 * APITB + p * 32);
            mma_bf16(out[2 * p + 0], a_hi, vh + 0);
            mma_bf16(out[2 * p + 0], a_hi, vl + 0);
            mma_bf16(out[2 * p + 0], a_lo, vh + 0);
            mma_bf16(out[2 * p + 1], a_hi, vh + 2);
            mma_bf16(out[2 * p + 1], a_hi, vl + 2);
            mma_bf16(out[2 * p + 1], a_lo, vh + 2);
        }
    }

    const size_t rb0 = ((size_t)(b << 12) + pi * WSZ + i0) * DMODEL + h * DHD + 2 * c;
    const size_t rb1 = ((size_t)(b << 12) + pi * WSZ + i1) * DMODEL + h * DHD + 2 * c;
#pragma unroll
    for (int p = 0; p < 8; p++) {
        const float v0 = out[p][0], v1 = out[p][1];
        unsigned hh = packf2(v0, v1);
        float r0 = __uint_as_float(hh << 16), r1 = __uint_as_float(hh & 0xffff0000u);
        *(unsigned*)&g_ahi[rb0 + p * 8] = hh;
        *(unsigned*)&g_alo[rb0 + p * 8] = packf2(v0 - r0, v1 - r1);
        const float u0 = out[p][2], u1 = out[p][3];
        unsigned hh1 = packf2(u0, u1);
        float s0 = __uint_as_float(hh1 << 16), s1 = __uint_as_float(hh1 & 0xffff0000u);
        *(unsigned*)&g_ahi[rb1 + p * 8] = hh1;
        *(unsigned*)&g_alo[rb1 + p * 8] = packf2(u0 - s0, u1 - s1);
    }
}

// ---------------------------------------------------------------------------
extern "C" void kernel_launch(void* const* d_in, const int* in_sizes, int n_in,
                              void* d_out, int out_size)
{
    const float* x       = (const float*)d_in[0];
    const float* Wqkv    = (const float*)d_in[1];
    const float* pos_emb = (const float*)d_in[2];
    const float* Wout    = (const float*)d_in[3];
    const float* bout    = (const float*)d_in[4];
    float* out = (float*)d_out;

    cudaFuncSetAttribute(gemm_bf16<0>, cudaFuncAttributeMaxDynamicSharedMemorySize, GSMEM_B);
    cudaFuncSetAttribute(gemm_bf16<1>, cudaFuncAttributeMaxDynamicSharedMemorySize, GSMEM_B);
    cudaFuncSetAttribute(attn_kernel, cudaFuncAttributeMaxDynamicSharedMemorySize, ATTN_SMEM_B);

    split_x_shift<<<MTOT, 128>>>(x);
    split_wT<0><<<dim3(QKV_LD / 32, DMODEL / 32), dim3(32, 32)>>>(Wqkv);
    split_wT<1><<<dim3(DMODEL / 32, DMODEL / 32), dim3(32, 32)>>>(Wout);

    gemm_bf16<0><<<dim3(6, 256), 256, GSMEM_B>>>(nullptr, nullptr);
    attn_kernel<<<2048, 256, ATTN_SMEM_B>>>(pos_emb);
    gemm_bf16<1><<<dim3(2, 256), 256, GSMEM_B>>>(bout, out);
}

// round 8
// speedup vs baseline: 1.0689x; 1.0689x over previous
#include <cuda_runtime.h>
#include <cuda_bf16.h>

#define NTOK   4096
#define DMODEL 512
#define NH     8
#define DHD    64
#define WSZ    128
#define NP     32
#define DISP   64
#define QKV_LD 1536
#define MTOT   32768

// ---------------------------------------------------------------------------
// Scratch (device globals — allocation-free per harness rules)
// ---------------------------------------------------------------------------
__device__ float g_qkv[(size_t)MTOT * QKV_LD];            // gemm0 out (f32)
__device__ __nv_bfloat16 g_xhi[(size_t)MTOT * DMODEL];    // shifted x, hi plane
__device__ __nv_bfloat16 g_xlo[(size_t)MTOT * DMODEL];    // shifted x, lo plane
__device__ __nv_bfloat16 g_ahi[(size_t)MTOT * DMODEL];    // attn out, hi plane
__device__ __nv_bfloat16 g_alo[(size_t)MTOT * DMODEL];    // attn out, lo plane
__device__ __nv_bfloat16 g_wqkv_hi[(size_t)QKV_LD * DMODEL];  // W^T [n][k]
__device__ __nv_bfloat16 g_wqkv_lo[(size_t)QKV_LD * DMODEL];
__device__ __nv_bfloat16 g_wout_hi[(size_t)DMODEL * DMODEL];
__device__ __nv_bfloat16 g_wout_lo[(size_t)DMODEL * DMODEL];

// ---------------------------------------------------------------------------
// helpers
// ---------------------------------------------------------------------------
__device__ __forceinline__ unsigned smem_u32(const void* p) {
    return (unsigned)__cvta_generic_to_shared(p);
}
__device__ __forceinline__ unsigned pack2(__nv_bfloat16 a, __nv_bfloat16 b) {
    unsigned short ua = *(unsigned short*)&a, ub = *(unsigned short*)&b;
    return (unsigned)ua | ((unsigned)ub << 16);
}
__device__ __forceinline__ unsigned packf2(float a, float b) {
    __nv_bfloat162 v = __float22bfloat162_rn(make_float2(a, b));
    return *(unsigned*)&v;
}
__device__ __forceinline__ void mma_bf16(float* d, const unsigned* a, const unsigned* b) {
    asm volatile(
        "mma.sync.aligned.m16n8k16.row.col.f32.bf16.bf16.f32 "
        "{%0,%1,%2,%3}, {%4,%5,%6,%7}, {%8,%9}, {%0,%1,%2,%3};\n"
        : "+f"(d[0]), "+f"(d[1]), "+f"(d[2]), "+f"(d[3])
        : "r"(a[0]), "r"(a[1]), "r"(a[2]), "r"(a[3]), "r"(b[0]), "r"(b[1]));
}
__device__ __forceinline__ void ldsm4(unsigned* r, unsigned a) {
    asm volatile("ldmatrix.sync.aligned.m8n8.x4.shared.b16 {%0,%1,%2,%3}, [%4];"
        : "=r"(r[0]), "=r"(r[1]), "=r"(r[2]), "=r"(r[3]) : "r"(a));
}
__device__ __forceinline__ void ldsm4t(unsigned* r, unsigned a) {
    asm volatile("ldmatrix.sync.aligned.m8n8.x4.trans.shared.b16 {%0,%1,%2,%3}, [%4];"
        : "=r"(r[0]), "=r"(r[1]), "=r"(r[2]), "=r"(r[3]) : "r"(a));
}
#define CP16(dst, src) \
    asm volatile("cp.async.ca.shared.global [%0], [%1], 16;\n" :: "r"(dst), "l"(src))

// ---------------------------------------------------------------------------
// Prep 1: shifted x -> bf16 hi/lo planes.
// ---------------------------------------------------------------------------
__global__ void __launch_bounds__(128)
split_x_shift(const float* __restrict__ x)
{
    const int row = blockIdx.x;
    const int b = row >> 12, n = row & 4095;
    const float4* src = (const float4*)(x + (size_t)((b << 12) | ((n + DISP) & 4095)) * DMODEL);
    float4 v = src[threadIdx.x];
    __nv_bfloat16 h0 = __float2bfloat16(v.x), h1 = __float2bfloat16(v.y);
    __nv_bfloat16 h2 = __float2bfloat16(v.z), h3 = __float2bfloat16(v.w);
    __nv_bfloat16 l0 = __float2bfloat16(v.x - __bfloat162float(h0));
    __nv_bfloat16 l1 = __float2bfloat16(v.y - __bfloat162float(h1));
    __nv_bfloat16 l2 = __float2bfloat16(v.z - __bfloat162float(h2));
    __nv_bfloat16 l3 = __float2bfloat16(v.w - __bfloat162float(h3));
    const size_t o = (size_t)row * DMODEL + threadIdx.x * 4;
    *(uint2*)&g_xhi[o] = make_uint2(pack2(h0, h1), pack2(h2, h3));
    *(uint2*)&g_xlo[o] = make_uint2(pack2(l0, l1), pack2(l2, l3));
}

// ---------------------------------------------------------------------------
// Prep 2: W [K][N] -> W^T [N][K] bf16 hi/lo planes.
// ---------------------------------------------------------------------------
template<int WHICH>
__global__ void __launch_bounds__(1024)
split_wT(const float* __restrict__ W)
{
    constexpr int K = DMODEL;
    constexpr int N = (WHICH == 0) ? QKV_LD : DMODEL;
    __nv_bfloat16* hi = (WHICH == 0) ? g_wqkv_hi : g_wout_hi;
    __nv_bfloat16* lo = (WHICH == 0) ? g_wqkv_lo : g_wout_lo;

    __shared__ float t[32][33];
    const int n0 = blockIdx.x << 5, k0 = blockIdx.y << 5;
    const int tx = threadIdx.x, ty = threadIdx.y;
    t[ty][tx] = W[(size_t)(k0 + ty) * N + n0 + tx];
    __syncthreads();
    const float v = t[tx][ty];
    const size_t o = (size_t)(n0 + ty) * K + k0 + tx;
    __nv_bfloat16 h = __float2bfloat16(v);
    hi[o] = h;
    lo[o] = __float2bfloat16(v - __bfloat162float(h));
}

// ---------------------------------------------------------------------------
// 3-term bf16 GEMM. 128x128x16 block tile, 256 thr, warps 2(M)x4(N),
// warp tile 64x32. ldmatrix fragments. 3 smem buffers, 2 outstanding
// cp.async groups, ONE __syncthreads per ktile.
// MODE 0: A = g_x{hi,lo}, B = Wqkv^T, C = g_qkv            (grid 12 x 256)
// MODE 1: A = g_a{hi,lo}, B = Wout^T, C = out (+roll,bias) (grid 4 x 256)
// ---------------------------------------------------------------------------
#define PITCH   24
#define PITCHB  48
#define PL_B    (128 * PITCHB)      // 6144 bytes per plane
#define STAGE_B (4 * PL_B)          // 24576 bytes per stage (Ah|Al|Bh|Bl)
#define GSMEM_B (3 * STAGE_B)       // 73728
#define NKIT    (DMODEL / 16)       // 32

template<int MODE>
__global__ void __launch_bounds__(256)
gemm_bf16(const float* __restrict__ bias, float* __restrict__ Cout)
{
    const __nv_bfloat16* __restrict__ Ahi = (MODE == 0) ? g_xhi : g_ahi;
    const __nv_bfloat16* __restrict__ Alo = (MODE == 0) ? g_xlo : g_alo;
    const __nv_bfloat16* __restrict__ Bhi = (MODE == 0) ? g_wqkv_hi : g_wout_hi;
    const __nv_bfloat16* __restrict__ Blo = (MODE == 0) ? g_wqkv_lo : g_wout_lo;
    float* __restrict__ C = (MODE == 0) ? (float*)g_qkv : Cout;
    constexpr int LDC = (MODE == 0) ? QKV_LD : DMODEL;

    extern __shared__ __align__(16) char smg[];
    const unsigned sbase = smem_u32(smg);

    const int tid  = threadIdx.x;
    const int lane = tid & 31;
    const int wid  = tid >> 5;
    const int g    = lane >> 2;
    const int c    = lane & 3;
    const int wm   = (wid >> 2) * 64;
    const int wn   = (wid & 3) * 32;

    const int m0 = blockIdx.y << 7;
    const int n0 = blockIdx.x << 7;

    // cp.async mapping: thread -> (row = tid>>1, 16B half = tid&1)
    const int lr = tid >> 1;
    const int lh = (tid & 1) * 8;
    const size_t agm = (size_t)(m0 + lr) * DMODEL + lh;
    const size_t bgm = (size_t)(n0 + lr) * DMODEL + lh;
    const unsigned ld_off = (unsigned)(lr * PITCHB + lh * 2);
    const unsigned dAh = sbase + 0 * PL_B + ld_off;
    const unsigned dAl = sbase + 1 * PL_B + ld_off;
    const unsigned dBh = sbase + 2 * PL_B + ld_off;
    const unsigned dBl = sbase + 3 * PL_B + ld_off;

    // ldmatrix lane offsets (bytes)
    const unsigned aoff = (unsigned)((wm + (lane & 15)) * PITCHB + (lane & 16));
    const unsigned boff = (unsigned)((wn + (lane & 7) + ((lane & 16) >> 1)) * PITCHB
                                     + ((lane & 8) << 1));
    const unsigned lAh = sbase + 0 * PL_B + aoff;
    const unsigned lAl = sbase + 1 * PL_B + aoff;
    const unsigned lBh = sbase + 2 * PL_B + boff;
    const unsigned lBl = sbase + 3 * PL_B + boff;

    float acc[4][4][4];
#pragma unroll
    for (int mt = 0; mt < 4; mt++)
#pragma unroll
        for (int nt = 0; nt < 4; nt++)
#pragma unroll
            for (int i = 0; i < 4; i++) acc[mt][nt][i] = 0.f;

#define LOAD_STAGE(kt)                                                         \
    do {                                                                       \
        if ((kt) < NKIT) {                                                     \
            const unsigned so = (unsigned)((kt) % 3) * STAGE_B;                \
            const size_t ka = agm + (size_t)(kt) * 16;                         \
            const size_t kb = bgm + (size_t)(kt) * 16;                         \
            CP16(dAh + so, Ahi + ka);                                          \
            CP16(dAl + so, Alo + ka);                                          \
            CP16(dBh + so, Bhi + kb);                                          \
            CP16(dBl + so, Blo + kb);                                          \
        }                                                                      \
        asm volatile("cp.async.commit_group;\n");                              \
    } while (0)

    LOAD_STAGE(0);
    LOAD_STAGE(1);

#pragma unroll 1
    for (int kt = 0; kt < NKIT; kt++) {
        asm volatile("cp.async.wait_group 1;\n");   // group kt complete
        __syncthreads();                            // single barrier per ktile
        LOAD_STAGE(kt + 2);                         // stage (kt+2)%3 == (kt-1)%3, safe

        const unsigned so = (unsigned)(kt % 3) * STAGE_B;
        unsigned Ah[4][4], Al[4][4];
#pragma unroll
        for (int mt = 0; mt < 4; mt++) {
            ldsm4(Ah[mt], lAh + so + mt * 16 * PITCHB);
            ldsm4(Al[mt], lAl + so + mt * 16 * PITCHB);
        }
        unsigned Bh[2][4], Bl[2][4];
#pragma unroll
        for (int p = 0; p < 2; p++) {
            ldsm4(Bh[p], lBh + so + p * 16 * PITCHB);
            ldsm4(Bl[p], lBl + so + p * 16 * PITCHB);
        }
#pragma unroll
        for (int mt = 0; mt < 4; mt++)
#pragma unroll
            for (int nt = 0; nt < 4; nt++) {
                const unsigned* bh = &Bh[nt >> 1][(nt & 1) * 2];
                const unsigned* bl = &Bl[nt >> 1][(nt & 1) * 2];
                mma_bf16(acc[mt][nt], Al[mt], bh);
                mma_bf16(acc[mt][nt], Ah[mt], bl);
                mma_bf16(acc[mt][nt], Ah[mt], bh);
            }
    }
#undef LOAD_STAGE

    float2 bv[4];
    if (MODE == 1) {
#pragma unroll
        for (int nt = 0; nt < 4; nt++)
            bv[nt] = *(const float2*)&bias[n0 + wn + nt * 8 + 2 * c];
    }
#pragma unroll
    for (int mt = 0; mt < 4; mt++) {
#pragma unroll
        for (int half = 0; half < 2; half++) {
            const int row = m0 + wm + mt * 16 + g + half * 8;
            long crow;
            if (MODE == 1) {
                const int bb = row >> 12, nn = row & 4095;
                crow = (long)((bb << 12) | ((nn + DISP) & 4095)) * LDC;
            } else {
                crow = (long)row * LDC;
            }
#pragma unroll
            for (int nt = 0; nt < 4; nt++) {
                float x = acc[mt][nt][half * 2 + 0];
                float y = acc[mt][nt][half * 2 + 1];
                if (MODE == 1) { x += bv[nt].x; y += bv[nt].y; }
                *(float2*)&C[crow + n0 + wn + nt * 8 + 2 * c] = make_float2(x, y);
            }
        }
    }
}

// ---------------------------------------------------------------------------
// Tensor-core windowed attention (R5 — known good).
// ---------------------------------------------------------------------------
#define APIT 72
#define APITB (APIT * 2)
#define PLANE_B (128 * APITB)
#define ATTN_SMEM_B (6 * PLANE_B)

__global__ void __launch_bounds__(256)
attn_kernel(const float* __restrict__ pos_emb)
{
    extern __shared__ __align__(16) char smc[];
    __nv_bfloat16* Qh = (__nv_bfloat16*)(smc + 0 * PLANE_B);
    __nv_bfloat16* Ql = (__nv_bfloat16*)(smc + 1 * PLANE_B);
    __nv_bfloat16* Kh = (__nv_bfloat16*)(smc + 2 * PLANE_B);
    __nv_bfloat16* Kl = (__nv_bfloat16*)(smc + 3 * PLANE_B);
    __nv_bfloat16* Vh = (__nv_bfloat16*)(smc + 4 * PLANE_B);
    __nv_bfloat16* Vl = (__nv_bfloat16*)(smc + 5 * PLANE_B);
    __shared__ float pe[2 * WSZ - 1];

    const int tid  = threadIdx.x;
    const int lane = tid & 31;
    const int w    = tid >> 5;
    const int g    = lane >> 2;
    const int c    = lane & 3;
    const int blk  = blockIdx.x;
    const int pi   = blk & 31;
    const int h    = (blk >> 5) & 7;
    const int b    = blk >> 8;

    for (int i = tid; i < 2 * WSZ - 1; i += 256) pe[i] = pos_emb[i];

    {
        const int tok = tid >> 1;
        const int d0  = (tid & 1) * 32;
        const size_t rbase = ((size_t)(b << 12) + tok * NP + pi) * QKV_LD + h * DHD;
        const int so = tok * APIT;
#pragma unroll
        for (int j = 0; j < 8; j += 2) {
#pragma unroll
            for (int u = 0; u < 2; u++) {
                const int d = d0 + (j + u) * 4;
                float4 q = *(const float4*)&g_qkv[rbase + d];
                float4 k = *(const float4*)&g_qkv[rbase + 512 + d];
                float4 v = *(const float4*)&g_qkv[rbase + 1024 + d];
                q.x *= 0.125f; q.y *= 0.125f; q.z *= 0.125f; q.w *= 0.125f;
                unsigned qh01 = packf2(q.x, q.y), qh23 = packf2(q.z, q.w);
                float qr0 = __uint_as_float(qh01 << 16), qr1 = __uint_as_float(qh01 & 0xffff0000u);
                float qr2 = __uint_as_float(qh23 << 16), qr3 = __uint_as_float(qh23 & 0xffff0000u);
                *(uint2*)&Qh[so + d] = make_uint2(qh01, qh23);
                *(uint2*)&Ql[so + d] = make_uint2(packf2(q.x - qr0, q.y - qr1),
                                                  packf2(q.z - qr2, q.w - qr3));
                unsigned kh01 = packf2(k.x, k.y), kh23 = packf2(k.z, k.w);
                float kr0 = __uint_as_float(kh01 << 16), kr1 = __uint_as_float(kh01 & 0xffff0000u);
                float kr2 = __uint_as_float(kh23 << 16), kr3 = __uint_as_float(kh23 & 0xffff0000u);
                *(uint2*)&Kh[so + d] = make_uint2(kh01, kh23);
                *(uint2*)&Kl[so + d] = make_uint2(packf2(k.x - kr0, k.y - kr1),
                                                  packf2(k.z - kr2, k.w - kr3));
                unsigned vh01 = packf2(v.x, v.y), vh23 = packf2(v.z, v.w);
                float vr0 = __uint_as_float(vh01 << 16), vr1 = __uint_as_float(vh01 & 0xffff0000u);
                float vr2 = __uint_as_float(vh23 << 16), vr3 = __uint_as_float(vh23 & 0xffff0000u);
                *(uint2*)&Vh[so + d] = make_uint2(vh01, vh23);
                *(uint2*)&Vl[so + d] = make_uint2(packf2(v.x - vr0, v.y - vr1),
                                                  packf2(v.z - vr2, v.w - vr3));
            }
        }
    }
    __syncthreads();

    float accS[16][4];
#pragma unroll
    for (int nt = 0; nt < 16; nt++)
#pragma unroll
        for (int i = 0; i < 4; i++) accS[nt][i] = 0.f;

    const unsigned qoff = (unsigned)((w * 16 + (lane & 15)) * APITB + (lane & 16));
    const unsigned koff = (unsigned)(((lane & 7) + ((lane & 16) >> 1)) * APITB
                                     + ((lane & 8) << 1));
    const unsigned uQh = smem_u32(Qh) + qoff, uQl = smem_u32(Ql) + qoff;
    const unsigned uKh = smem_u32(Kh) + koff, uKl = smem_u32(Kl) + koff;

#pragma unroll
    for (int kc = 0; kc < 4; kc++) {
        unsigned qh[4], ql[4];
        ldsm4(qh, uQh + kc * 32);
        ldsm4(ql, uQl + kc * 32);
#pragma unroll
        for (int p = 0; p < 8; p++) {
            unsigned kh[4], kl[4];
            ldsm4(kh, uKh + p * 16 * APITB + kc * 32);
            ldsm4(kl, uKl + p * 16 * APITB + kc * 32);
            mma_bf16(accS[2 * p + 0], ql, kh + 0);
            mma_bf16(accS[2 * p + 0], qh, kl + 0);
            mma_bf16(accS[2 * p + 0], qh, kh + 0);
            mma_bf16(accS[2 * p + 1], ql, kh + 2);
            mma_bf16(accS[2 * p + 1], qh, kl + 2);
            mma_bf16(accS[2 * p + 1], qh, kh + 2);
        }
    }

    const int i0 = w * 16 + g;
    const int i1 = i0 + 8;
    const bool q0 = (i0 >= 64), q1 = (i1 >= 64);
    float mx0 = -3.0e38f, mx1 = -3.0e38f;
#pragma unroll
    for (int nt = 0; nt < 16; nt++) {
#pragma unroll
        for (int e = 0; e < 2; e++) {
            const int j = nt * 8 + 2 * c + e;
            const bool jq = (j >= 64);
            float s0 = accS[nt][e]     + pe[j - i0 + (WSZ - 1)];
            float s1 = accS[nt][2 + e] + pe[j - i1 + (WSZ - 1)];
            if (q0 != jq) s0 -= 1e9f;
            if (q1 != jq) s1 -= 1e9f;
            accS[nt][e] = s0;     mx0 = fmaxf(mx0, s0);
            accS[nt][2 + e] = s1; mx1 = fmaxf(mx1, s1);
        }
    }
    mx0 = fmaxf(mx0, __shfl_xor_sync(0xffffffffu, mx0, 1));
    mx0 = fmaxf(mx0, __shfl_xor_sync(0xffffffffu, mx0, 2));
    mx1 = fmaxf(mx1, __shfl_xor_sync(0xffffffffu, mx1, 1));
    mx1 = fmaxf(mx1, __shfl_xor_sync(0xffffffffu, mx1, 2));
    float sm0 = 0.f, sm1 = 0.f;
#pragma unroll
    for (int nt = 0; nt < 16; nt++) {
#pragma unroll
        for (int e = 0; e < 2; e++) {
            float e0 = __expf(accS[nt][e] - mx0);
            float e1 = __expf(accS[nt][2 + e] - mx1);
            accS[nt][e] = e0;     sm0 += e0;
            accS[nt][2 + e] = e1; sm1 += e1;
        }
    }
    sm0 += __shfl_xor_sync(0xffffffffu, sm0, 1);
    sm0 += __shfl_xor_sync(0xffffffffu, sm0, 2);
    sm1 += __shfl_xor_sync(0xffffffffu, sm1, 1);
    sm1 += __shfl_xor_sync(0xffffffffu, sm1, 2);
    const float inv0 = 1.0f / sm0, inv1 = 1.0f / sm1;
#pragma unroll
    for (int nt = 0; nt < 16; nt++) {
        accS[nt][0] *= inv0; accS[nt][1] *= inv0;
        accS[nt][2] *= inv1; accS[nt][3] *= inv1;
    }

    float out[8][4];
#pragma unroll
    for (int nt = 0; nt < 8; nt++)
#pragma unroll
        for (int i = 0; i < 4; i++) out[nt][i] = 0.f;

    const unsigned voff = (unsigned)((lane & 15) * APITB + (lane & 16));
    const unsigned uVh = smem_u32(Vh) + voff, uVl = smem_u32(Vl) + voff;

#pragma unroll
    for (int kc = 0; kc < 8; kc++) {
        unsigned a_hi[4], a_lo[4];
#pragma unroll
        for (int q = 0; q < 4; q++) {
            const int nt = 2 * kc + (q >> 1);
            const int e0 = (q & 1) * 2;
            const float v0 = accS[nt][e0], v1 = accS[nt][e0 + 1];
            const unsigned hh = packf2(v0, v1);
            a_hi[q] = hh;
            const float r0 = __uint_as_float(hh << 16);
            const float r1 = __uint_as_float(hh & 0xffff0000u);
            a_lo[q] = packf2(v0 - r0, v1 - r1);
        }
#pragma unroll
        for (int p = 0; p < 4; p++) {
            unsigned vh[4], vl[4];
            ldsm4t(vh, uVh + kc * 16 * APITB + p * 32);
            ldsm4t(vl, uVl + kc * 16 * APITB + p * 32);
            mma_bf16(out[2 * p + 0], a_hi, vh + 0);
            mma_bf16(out[2 * p + 0], a_hi, vl + 0);
            mma_bf16(out[2 * p + 0], a_lo, vh + 0);
            mma_bf16(out[2 * p + 1], a_hi, vh + 2);
            mma_bf16(out[2 * p + 1], a_hi, vl + 2);
            mma_bf16(out[2 * p + 1], a_lo, vh + 2);
        }
    }

    const size_t rb0 = ((size_t)(b << 12) + pi * WSZ + i0) * DMODEL + h * DHD + 2 * c;
    const size_t rb1 = ((size_t)(b << 12) + pi * WSZ + i1) * DMODEL + h * DHD + 2 * c;
#pragma unroll
    for (int p = 0; p < 8; p++) {
        const float v0 = out[p][0], v1 = out[p][1];
        unsigned hh = packf2(v0, v1);
        float r0 = __uint_as_float(hh << 16), r1 = __uint_as_float(hh & 0xffff0000u);
        *(unsigned*)&g_ahi[rb0 + p * 8] = hh;
        *(unsigned*)&g_alo[rb0 + p * 8] = packf2(v0 - r0, v1 - r1);
        const float u0 = out[p][2], u1 = out[p][3];
        unsigned hh1 = packf2(u0, u1);
        float s0 = __uint_as_float(hh1 << 16), s1 = __uint_as_float(hh1 & 0xffff0000u);
        *(unsigned*)&g_ahi[rb1 + p * 8] = hh1;
        *(unsigned*)&g_alo[rb1 + p * 8] = packf2(u0 - s0, u1 - s1);
    }
}

// ---------------------------------------------------------------------------
extern "C" void kernel_launch(void* const* d_in, const int* in_sizes, int n_in,
                              void* d_out, int out_size)
{
    const float* x       = (const float*)d_in[0];
    const float* Wqkv    = (const float*)d_in[1];
    const float* pos_emb = (const float*)d_in[2];
    const float* Wout    = (const float*)d_in[3];
    const float* bout    = (const float*)d_in[4];
    float* out = (float*)d_out;

    cudaFuncSetAttribute(gemm_bf16<0>, cudaFuncAttributeMaxDynamicSharedMemorySize, GSMEM_B);
    cudaFuncSetAttribute(gemm_bf16<1>, cudaFuncAttributeMaxDynamicSharedMemorySize, GSMEM_B);
    cudaFuncSetAttribute(attn_kernel, cudaFuncAttributeMaxDynamicSharedMemorySize, ATTN_SMEM_B);

    split_x_shift<<<MTOT, 128>>>(x);
    split_wT<0><<<dim3(QKV_LD / 32, DMODEL / 32), dim3(32, 32)>>>(Wqkv);
    split_wT<1><<<dim3(DMODEL / 32, DMODEL / 32), dim3(32, 32)>>>(Wout);

    gemm_bf16<0><<<dim3(12, 256), 256, GSMEM_B>>>(nullptr, nullptr);
    attn_kernel<<<2048, 256, ATTN_SMEM_B>>>(pos_emb);
    gemm_bf16<1><<<dim3(4, 256), 256, GSMEM_B>>>(bout, out);
}